// round 3
// baseline (speedup 1.0000x reference)
#include <cuda_runtime.h>
#include <math.h>

#define THREADS 512
typedef unsigned long long ull;

// ---- shared memory layout (float offsets) ----
#define XBUF_OFF 0            // [64][256] activations
#define EMB_OFF  16384        // [64][64]  xyz harmonic emb (cols 0..31 reused for dir emb)
#define WS_OFF   20480        // float2[2][16][256] double-buffered weight chunks, kk2-major
#define DENS_OFF 36864        // [64] density
#define EMBD_OFF 36928        // [32] per-ray dir emb scratch
#define SMEM_FLOATS 36960
#define SMEM_BYTES (SMEM_FLOATS * 4)

// Blackwell packed fp32 FMA: d.{lo,hi} += a.{lo,hi} * b.{lo,hi}
__device__ __forceinline__ void fma2(ull& d, ull a, ull b) {
    asm("fma.rn.f32x2 %0, %1, %2, %0;" : "+l"(d) : "l"(a), "l"(b));
}

// Stage one 32-wide k-chunk of W (OUTW rows) into ws2 as kk2-major float2 pairs.
// o-fast index mapping: STS conflict-free (consecutive lanes -> consecutive o).
template<int OUTW>
__device__ __forceinline__ void stage_chunk(const float* __restrict__ Wg, int in_act,
                                            int k0, float2* __restrict__ dst, int tid) {
#pragma unroll 1
    for (int idx = tid; idx < OUTW * 16; idx += THREADS) {
        int o   = idx & (OUTW - 1);
        int kk2 = idx / OUTW;
        int k   = k0 + (kk2 << 1);
        const float* row = Wg + o * in_act;
        float2 v;
        v.x = (k     < in_act) ? __ldg(row + k)     : 0.0f;
        v.y = (k + 1 < in_act) ? __ldg(row + k + 1) : 0.0f;
        dst[kk2 * 256 + o] = v;
    }
}

// Fused layer: xbuf[64][OUT] = relu(A * W^T + b). A chunks from xbuf then emb.
// 16 warps: warp&7 -> m-block (8 rows), warp>>3 -> o-half. Per-thread tile 8m x NJ2 o.
// k in pairs; f32x2 accumulator halves hold even/odd-k partial sums, folded at writeback.
template<int NJ2>
__device__ __forceinline__ void gemm_layer(
    const float* __restrict__ Wg, const float* __restrict__ bg,
    int in_act, int nchunks, int xchunks,
    float* xbuf, float* emb, float2* ws2)
{
    constexpr int OUTW = NJ2 * 64;
    const int tid   = threadIdx.x;
    const int lane  = tid & 31;
    const int warp  = tid >> 5;
    const int mb    = (warp & 7) << 3;
    const int obase = lane + (((warp >> 3) * NJ2) << 5);

    ull acc[8][NJ2];
#pragma unroll
    for (int i = 0; i < 8; ++i)
#pragma unroll
        for (int j = 0; j < NJ2; ++j) acc[i][j] = 0ull;

    // prologue: stage chunk 0 into buffer 0 (only reads global, writes ws buf0)
    stage_chunk<OUTW>(Wg, in_act, 0, ws2, tid);

#pragma unroll 1
    for (int c = 0; c < nchunks; ++c) {
        __syncthreads();   // chunk c staged; prev iteration's reads of buf((c+1)&1) done
        if (c + 1 < nchunks)
            stage_chunk<OUTW>(Wg, in_act, (c + 1) << 5, ws2 + ((c + 1) & 1) * 4096, tid);

        const float* As; int lda;
        if (c < xchunks) { As = xbuf + (c << 5);                  lda = 256; }
        else             { As = emb  + ((c - xchunks) << 5);      lda = 64;  }
        const float2* wb = ws2 + (c & 1) * 4096;

#pragma unroll 1
        for (int kk4 = 0; kk4 < 8; ++kk4) {    // 4 k per iter (two k-pairs)
            ull aL[8], aH[8];
#pragma unroll
            for (int i = 0; i < 8; ++i) {      // warp-uniform -> broadcast LDS.128
                ulonglong2 v = *reinterpret_cast<const ulonglong2*>(
                    As + (mb + i) * lda + (kk4 << 2));
                aL[i] = v.x; aH[i] = v.y;
            }
#pragma unroll
            for (int j = 0; j < NJ2; ++j) {
                ull w = *reinterpret_cast<const ull*>(wb + ((kk4 << 1)) * 256 + obase + (j << 5));
#pragma unroll
                for (int i = 0; i < 8; ++i) fma2(acc[i][j], aL[i], w);
            }
#pragma unroll
            for (int j = 0; j < NJ2; ++j) {
                ull w = *reinterpret_cast<const ull*>(wb + ((kk4 << 1) + 1) * 256 + obase + (j << 5));
#pragma unroll
                for (int i = 0; i < 8; ++i) fma2(acc[i][j], aH[i], w);
            }
        }
    }
    __syncthreads();   // all reads of xbuf done before overwrite
#pragma unroll
    for (int j = 0; j < NJ2; ++j) {
        const int o = obase + (j << 5);
        const float bias = __ldg(bg + o);
#pragma unroll
        for (int i = 0; i < 8; ++i) {
            float lo = __uint_as_float((unsigned)(acc[i][j] & 0xffffffffull));
            float hi = __uint_as_float((unsigned)(acc[i][j] >> 32));
            xbuf[(mb + i) * 256 + o] = fmaxf(lo + hi + bias, 0.0f);
        }
    }
    __syncthreads();
}

__global__ void __launch_bounds__(THREADS, 1) nerf_fused(
    const float* __restrict__ sp,   const float* __restrict__ dirs,
    const float* __restrict__ Wx0,  const float* __restrict__ bx0,
    const float* __restrict__ Wx1,  const float* __restrict__ bx1,
    const float* __restrict__ Wx2,  const float* __restrict__ bx2,
    const float* __restrict__ Wx3,  const float* __restrict__ bx3,
    const float* __restrict__ Wx4,  const float* __restrict__ bx4,
    const float* __restrict__ Wx5,  const float* __restrict__ bx5,
    const float* __restrict__ Wx6,  const float* __restrict__ bx6,
    const float* __restrict__ Wx7,  const float* __restrict__ bx7,
    const float* __restrict__ Wd0,  const float* __restrict__ bd0,
    const float* __restrict__ Wden, const float* __restrict__ bden,
    const float* __restrict__ Wfeat,const float* __restrict__ bfeat,
    const float* __restrict__ Wrgb, const float* __restrict__ brgb,
    float* __restrict__ out)
{
    extern __shared__ float sm[];
    float*  xbuf = sm + XBUF_OFF;
    float*  emb  = sm + EMB_OFF;
    float2* ws2  = reinterpret_cast<float2*>(sm + WS_OFF);
    float*  dens = sm + DENS_OFF;
    float*  embd = sm + EMBD_OFF;

    const int tid  = threadIdx.x;
    const int lane = tid & 31;
    const int warp = tid >> 5;
    const int p0   = blockIdx.x << 6;   // one ray (64 samples) per block

    // ---- Phase 0: xyz harmonic embedding [sin(30), cos(30), xyz(3), pad0] ----
    if (tid < 64) {
        const float* pp = sp + (size_t)(p0 + tid) * 3;
        float* e = emb + tid * 64;
#pragma unroll
        for (int d = 0; d < 3; ++d) {
            float x = pp[d];
            float f = 1.0f;
#pragma unroll
            for (int h = 0; h < 10; ++h) {
                float s, c;
                sincosf(x * f, &s, &c);
                e[d * 10 + h]      = s;
                e[30 + d * 10 + h] = c;
                f *= 2.0f;
            }
            e[60 + d] = x;
        }
        e[63] = 0.0f;
    }
    // gemm_layer's loop-top __syncthreads orders phase 0 vs first compute

    gemm_layer<4>(Wx0, bx0,  63,  2, 0, xbuf, emb, ws2);   // 63->256 (from emb)
    gemm_layer<4>(Wx1, bx1, 256,  8, 8, xbuf, emb, ws2);
    gemm_layer<4>(Wx2, bx2, 256,  8, 8, xbuf, emb, ws2);
    gemm_layer<4>(Wx3, bx3, 256,  8, 8, xbuf, emb, ws2);
    gemm_layer<4>(Wx4, bx4, 319, 10, 8, xbuf, emb, ws2);   // skip: [h(256), emb_x(63)]
    gemm_layer<4>(Wx5, bx5, 256,  8, 8, xbuf, emb, ws2);
    gemm_layer<4>(Wx6, bx6, 256,  8, 8, xbuf, emb, ws2);
    gemm_layer<4>(Wx7, bx7, 256,  8, 8, xbuf, emb, ws2);

    // ---- density head (reads xbuf before feat overwrites it) ----
    {
        const float bd = __ldg(bden);
#pragma unroll 1
        for (int it = 0; it < 4; ++it) {
            int m = warp + (it << 4);
            float s = 0.0f;
#pragma unroll
            for (int kk = 0; kk < 8; ++kk) {
                int k = lane + (kk << 5);
                s += xbuf[m * 256 + k] * __ldg(Wden + k);
            }
#pragma unroll
            for (int off = 16; off > 0; off >>= 1) s += __shfl_xor_sync(0xffffffffu, s, off);
            if (lane == 0) dens[m] = fmaxf(s + bd, 0.0f);
        }
    }
    __syncthreads();

    gemm_layer<4>(Wfeat, bfeat, 256, 8, 8, xbuf, emb, ws2);

    // ---- direction embedding [sin(12), cos(12), dir(3), pad0] -> emb cols 0..31 ----
    if (tid < 32) {
        float v = 0.0f;
        if (tid < 12) {
            float x = __ldg(dirs + blockIdx.x * 3 + (tid >> 2));
            v = sinf(x * (float)(1 << (tid & 3)));
        } else if (tid < 24) {
            int kk = tid - 12;
            float x = __ldg(dirs + blockIdx.x * 3 + (kk >> 2));
            v = cosf(x * (float)(1 << (kk & 3)));
        } else if (tid < 27) {
            v = __ldg(dirs + blockIdx.x * 3 + (tid - 24));
        }
        embd[tid] = v;
    }
    __syncthreads();
    for (int idx = tid; idx < 64 * 32; idx += THREADS)
        emb[(idx >> 5) * 64 + (idx & 31)] = embd[idx & 31];

    gemm_layer<2>(Wd0, bd0, 283, 9, 8, xbuf, emb, ws2);    // [feat(256), emb_d(27)] -> 128

    // ---- rgb head + output ----
    {
#pragma unroll 1
        for (int it = 0; it < 4; ++it) {
            int m = warp + (it << 4);
            float s0 = 0.0f, s1 = 0.0f, s2 = 0.0f;
#pragma unroll
            for (int kk = 0; kk < 4; ++kk) {
                int k = lane + (kk << 5);
                float h = xbuf[m * 256 + k];
                s0 += h * __ldg(Wrgb + k);
                s1 += h * __ldg(Wrgb + 128 + k);
                s2 += h * __ldg(Wrgb + 256 + k);
            }
#pragma unroll
            for (int off = 16; off > 0; off >>= 1) {
                s0 += __shfl_xor_sync(0xffffffffu, s0, off);
                s1 += __shfl_xor_sync(0xffffffffu, s1, off);
                s2 += __shfl_xor_sync(0xffffffffu, s2, off);
            }
            if (lane == 0) {
                float* op = out + (size_t)(p0 + m) * 4;
                op[0] = dens[m];
                op[1] = 1.0f / (1.0f + expf(-(s0 + __ldg(brgb))));
                op[2] = 1.0f / (1.0f + expf(-(s1 + __ldg(brgb + 1))));
                op[3] = 1.0f / (1.0f + expf(-(s2 + __ldg(brgb + 2))));
            }
        }
    }
}

extern "C" void kernel_launch(void* const* d_in, const int* in_sizes, int n_in,
                              void* d_out, int out_size) {
    (void)in_sizes; (void)n_in; (void)out_size;
    cudaFuncSetAttribute(nerf_fused, cudaFuncAttributeMaxDynamicSharedMemorySize, SMEM_BYTES);
    nerf_fused<<<4096, THREADS, SMEM_BYTES>>>(
        (const float*)d_in[0],  (const float*)d_in[1],
        (const float*)d_in[2],  (const float*)d_in[3],
        (const float*)d_in[4],  (const float*)d_in[5],
        (const float*)d_in[6],  (const float*)d_in[7],
        (const float*)d_in[8],  (const float*)d_in[9],
        (const float*)d_in[10], (const float*)d_in[11],
        (const float*)d_in[12], (const float*)d_in[13],
        (const float*)d_in[14], (const float*)d_in[15],
        (const float*)d_in[16], (const float*)d_in[17],
        (const float*)d_in[18], (const float*)d_in[19],
        (const float*)d_in[20], (const float*)d_in[21],
        (const float*)d_in[22], (const float*)d_in[23],
        (const float*)d_in[24], (const float*)d_in[25],
        (float*)d_out);
}

// round 4
// speedup vs baseline: 1.0003x; 1.0003x over previous
#include <cuda_runtime.h>
#include <math.h>

#define THREADS 512
typedef unsigned long long ull;

// ---- shared memory layout (float offsets) ----
#define XBUF_OFF 0            // [64][256] activations
#define EMB_OFF  16384        // [64][64]  xyz harmonic emb (cols 0..31 reused for dir emb)
#define WS_OFF   20480        // float2[2][16][256] double-buffered weight chunks, kk2-major
#define DENS_OFF 36864        // [64] density
#define EMBD_OFF 36928        // [32] per-ray dir emb scratch
#define SMEM_FLOATS 36960
#define SMEM_BYTES (SMEM_FLOATS * 4)

// Blackwell packed fp32 FMA: d.{lo,hi} += a.{lo,hi} * b.{lo,hi}
__device__ __forceinline__ void fma2(ull& d, ull a, ull b) {
    asm("fma.rn.f32x2 %0, %1, %2, %0;" : "+l"(d) : "l"(a), "l"(b));
}

// Stage one 32-wide k-chunk of W (OUTW rows) into ws2 as kk2-major float2 pairs.
// o-fast index mapping: STS conflict-free (consecutive lanes -> consecutive o).
template<int OUTW>
__device__ __forceinline__ void stage_chunk(const float* __restrict__ Wg, int in_act,
                                            int k0, float2* __restrict__ dst, int tid) {
#pragma unroll 1
    for (int idx = tid; idx < OUTW * 16; idx += THREADS) {
        int o   = idx & (OUTW - 1);
        int kk2 = idx / OUTW;
        int k   = k0 + (kk2 << 1);
        const float* row = Wg + o * in_act;
        float2 v;
        v.x = (k     < in_act) ? __ldg(row + k)     : 0.0f;
        v.y = (k + 1 < in_act) ? __ldg(row + k + 1) : 0.0f;
        dst[kk2 * 256 + o] = v;
    }
}

// Fused layer: xbuf[64][OUT] = relu(A * W^T + b). A chunks from xbuf then emb.
// 16 warps: warp&7 -> m-block (8 rows), warp>>3 -> o-half. Per-thread tile 8m x NJ2 o.
// k in pairs; f32x2 accumulator halves hold even/odd-k partial sums, folded at writeback.
template<int NJ2>
__device__ __forceinline__ void gemm_layer(
    const float* __restrict__ Wg, const float* __restrict__ bg,
    int in_act, int nchunks, int xchunks,
    float* xbuf, float* emb, float2* ws2)
{
    constexpr int OUTW = NJ2 * 64;
    const int tid   = threadIdx.x;
    const int lane  = tid & 31;
    const int warp  = tid >> 5;
    const int mb    = (warp & 7) << 3;
    const int obase = lane + (((warp >> 3) * NJ2) << 5);

    ull acc[8][NJ2];
#pragma unroll
    for (int i = 0; i < 8; ++i)
#pragma unroll
        for (int j = 0; j < NJ2; ++j) acc[i][j] = 0ull;

    // prologue: stage chunk 0 into buffer 0 (only reads global, writes ws buf0)
    stage_chunk<OUTW>(Wg, in_act, 0, ws2, tid);

#pragma unroll 1
    for (int c = 0; c < nchunks; ++c) {
        __syncthreads();   // chunk c staged; prev iteration's reads of buf((c+1)&1) done
        if (c + 1 < nchunks)
            stage_chunk<OUTW>(Wg, in_act, (c + 1) << 5, ws2 + ((c + 1) & 1) * 4096, tid);

        const float* As; int lda;
        if (c < xchunks) { As = xbuf + (c << 5);                  lda = 256; }
        else             { As = emb  + ((c - xchunks) << 5);      lda = 64;  }
        const float2* wb = ws2 + (c & 1) * 4096;

#pragma unroll 1
        for (int kk4 = 0; kk4 < 8; ++kk4) {    // 4 k per iter (two k-pairs)
            ull aL[8], aH[8];
#pragma unroll
            for (int i = 0; i < 8; ++i) {      // warp-uniform -> broadcast LDS.128
                ulonglong2 v = *reinterpret_cast<const ulonglong2*>(
                    As + (mb + i) * lda + (kk4 << 2));
                aL[i] = v.x; aH[i] = v.y;
            }
#pragma unroll
            for (int j = 0; j < NJ2; ++j) {
                ull w = *reinterpret_cast<const ull*>(wb + ((kk4 << 1)) * 256 + obase + (j << 5));
#pragma unroll
                for (int i = 0; i < 8; ++i) fma2(acc[i][j], aL[i], w);
            }
#pragma unroll
            for (int j = 0; j < NJ2; ++j) {
                ull w = *reinterpret_cast<const ull*>(wb + ((kk4 << 1) + 1) * 256 + obase + (j << 5));
#pragma unroll
                for (int i = 0; i < 8; ++i) fma2(acc[i][j], aH[i], w);
            }
        }
    }
    __syncthreads();   // all reads of xbuf done before overwrite
#pragma unroll
    for (int j = 0; j < NJ2; ++j) {
        const int o = obase + (j << 5);
        const float bias = __ldg(bg + o);
#pragma unroll
        for (int i = 0; i < 8; ++i) {
            float lo = __uint_as_float((unsigned)(acc[i][j] & 0xffffffffull));
            float hi = __uint_as_float((unsigned)(acc[i][j] >> 32));
            xbuf[(mb + i) * 256 + o] = fmaxf(lo + hi + bias, 0.0f);
        }
    }
    __syncthreads();
}

__global__ void __launch_bounds__(THREADS, 1) nerf_fused(
    const float* __restrict__ sp,   const float* __restrict__ dirs,
    const float* __restrict__ Wx0,  const float* __restrict__ bx0,
    const float* __restrict__ Wx1,  const float* __restrict__ bx1,
    const float* __restrict__ Wx2,  const float* __restrict__ bx2,
    const float* __restrict__ Wx3,  const float* __restrict__ bx3,
    const float* __restrict__ Wx4,  const float* __restrict__ bx4,
    const float* __restrict__ Wx5,  const float* __restrict__ bx5,
    const float* __restrict__ Wx6,  const float* __restrict__ bx6,
    const float* __restrict__ Wx7,  const float* __restrict__ bx7,
    const float* __restrict__ Wd0,  const float* __restrict__ bd0,
    const float* __restrict__ Wden, const float* __restrict__ bden,
    const float* __restrict__ Wfeat,const float* __restrict__ bfeat,
    const float* __restrict__ Wrgb, const float* __restrict__ brgb,
    float* __restrict__ out)
{
    extern __shared__ float sm[];
    float*  xbuf = sm + XBUF_OFF;
    float*  emb  = sm + EMB_OFF;
    float2* ws2  = reinterpret_cast<float2*>(sm + WS_OFF);
    float*  dens = sm + DENS_OFF;
    float*  embd = sm + EMBD_OFF;

    const int tid  = threadIdx.x;
    const int lane = tid & 31;
    const int warp = tid >> 5;
    const int p0   = blockIdx.x << 6;   // one ray (64 samples) per block

    // ---- Phase 0: xyz harmonic embedding [sin(30), cos(30), xyz(3), pad0] ----
    if (tid < 64) {
        const float* pp = sp + (size_t)(p0 + tid) * 3;
        float* e = emb + tid * 64;
#pragma unroll
        for (int d = 0; d < 3; ++d) {
            float x = pp[d];
            float f = 1.0f;
#pragma unroll
            for (int h = 0; h < 10; ++h) {
                float s, c;
                sincosf(x * f, &s, &c);
                e[d * 10 + h]      = s;
                e[30 + d * 10 + h] = c;
                f *= 2.0f;
            }
            e[60 + d] = x;
        }
        e[63] = 0.0f;
    }
    // gemm_layer's loop-top __syncthreads orders phase 0 vs first compute

    gemm_layer<4>(Wx0, bx0,  63,  2, 0, xbuf, emb, ws2);   // 63->256 (from emb)
    gemm_layer<4>(Wx1, bx1, 256,  8, 8, xbuf, emb, ws2);
    gemm_layer<4>(Wx2, bx2, 256,  8, 8, xbuf, emb, ws2);
    gemm_layer<4>(Wx3, bx3, 256,  8, 8, xbuf, emb, ws2);
    gemm_layer<4>(Wx4, bx4, 319, 10, 8, xbuf, emb, ws2);   // skip: [h(256), emb_x(63)]
    gemm_layer<4>(Wx5, bx5, 256,  8, 8, xbuf, emb, ws2);
    gemm_layer<4>(Wx6, bx6, 256,  8, 8, xbuf, emb, ws2);
    gemm_layer<4>(Wx7, bx7, 256,  8, 8, xbuf, emb, ws2);

    // ---- density head (reads xbuf before feat overwrites it) ----
    {
        const float bd = __ldg(bden);
#pragma unroll 1
        for (int it = 0; it < 4; ++it) {
            int m = warp + (it << 4);
            float s = 0.0f;
#pragma unroll
            for (int kk = 0; kk < 8; ++kk) {
                int k = lane + (kk << 5);
                s += xbuf[m * 256 + k] * __ldg(Wden + k);
            }
#pragma unroll
            for (int off = 16; off > 0; off >>= 1) s += __shfl_xor_sync(0xffffffffu, s, off);
            if (lane == 0) dens[m] = fmaxf(s + bd, 0.0f);
        }
    }
    __syncthreads();

    gemm_layer<4>(Wfeat, bfeat, 256, 8, 8, xbuf, emb, ws2);

    // ---- direction embedding [sin(12), cos(12), dir(3), pad0] -> emb cols 0..31 ----
    if (tid < 32) {
        float v = 0.0f;
        if (tid < 12) {
            float x = __ldg(dirs + blockIdx.x * 3 + (tid >> 2));
            v = sinf(x * (float)(1 << (tid & 3)));
        } else if (tid < 24) {
            int kk = tid - 12;
            float x = __ldg(dirs + blockIdx.x * 3 + (kk >> 2));
            v = cosf(x * (float)(1 << (kk & 3)));
        } else if (tid < 27) {
            v = __ldg(dirs + blockIdx.x * 3 + (tid - 24));
        }
        embd[tid] = v;
    }
    __syncthreads();
    for (int idx = tid; idx < 64 * 32; idx += THREADS)
        emb[(idx >> 5) * 64 + (idx & 31)] = embd[idx & 31];

    gemm_layer<2>(Wd0, bd0, 283, 9, 8, xbuf, emb, ws2);    // [feat(256), emb_d(27)] -> 128

    // ---- rgb head + output ----
    {
#pragma unroll 1
        for (int it = 0; it < 4; ++it) {
            int m = warp + (it << 4);
            float s0 = 0.0f, s1 = 0.0f, s2 = 0.0f;
#pragma unroll
            for (int kk = 0; kk < 4; ++kk) {
                int k = lane + (kk << 5);
                float h = xbuf[m * 256 + k];
                s0 += h * __ldg(Wrgb + k);
                s1 += h * __ldg(Wrgb + 128 + k);
                s2 += h * __ldg(Wrgb + 256 + k);
            }
#pragma unroll
            for (int off = 16; off > 0; off >>= 1) {
                s0 += __shfl_xor_sync(0xffffffffu, s0, off);
                s1 += __shfl_xor_sync(0xffffffffu, s1, off);
                s2 += __shfl_xor_sync(0xffffffffu, s2, off);
            }
            if (lane == 0) {
                float* op = out + (size_t)(p0 + m) * 4;
                op[0] = dens[m];
                op[1] = 1.0f / (1.0f + expf(-(s0 + __ldg(brgb))));
                op[2] = 1.0f / (1.0f + expf(-(s1 + __ldg(brgb + 1))));
                op[3] = 1.0f / (1.0f + expf(-(s2 + __ldg(brgb + 2))));
            }
        }
    }
}

extern "C" void kernel_launch(void* const* d_in, const int* in_sizes, int n_in,
                              void* d_out, int out_size) {
    (void)in_sizes; (void)n_in; (void)out_size;
    cudaFuncSetAttribute(nerf_fused, cudaFuncAttributeMaxDynamicSharedMemorySize, SMEM_BYTES);
    nerf_fused<<<4096, THREADS, SMEM_BYTES>>>(
        (const float*)d_in[0],  (const float*)d_in[1],
        (const float*)d_in[2],  (const float*)d_in[3],
        (const float*)d_in[4],  (const float*)d_in[5],
        (const float*)d_in[6],  (const float*)d_in[7],
        (const float*)d_in[8],  (const float*)d_in[9],
        (const float*)d_in[10], (const float*)d_in[11],
        (const float*)d_in[12], (const float*)d_in[13],
        (const float*)d_in[14], (const float*)d_in[15],
        (const float*)d_in[16], (const float*)d_in[17],
        (const float*)d_in[18], (const float*)d_in[19],
        (const float*)d_in[20], (const float*)d_in[21],
        (const float*)d_in[22], (const float*)d_in[23],
        (const float*)d_in[24], (const float*)d_in[25],
        (float*)d_out);
}

// round 5
// speedup vs baseline: 1.2842x; 1.2838x over previous
#include <cuda_runtime.h>
#include <math.h>

#define THREADS 256
typedef unsigned long long ull;

// ---- shared memory layout (float offsets) ----
#define XBUF_OFF 0            // [64][256] activations
#define EMB_OFF  16384        // [64][64]  xyz harmonic emb (cols 0..31 reused for dir emb)
#define WS_OFF   20480        // float2[2][16][256] double-buffered weights, kk-major + 256 float2 overread pad
#define DENS_OFF 37376        // [64] density
#define EMBD_OFF 37440        // [32] per-ray dir emb scratch
#define SMEM_FLOATS 37472
#define SMEM_BYTES (SMEM_FLOATS * 4)

// Blackwell packed fp32 FMA: d.{lo,hi} += a.{lo,hi} * b.{lo,hi}
__device__ __forceinline__ void fma2(ull& d, ull a, ull b) {
    asm("fma.rn.f32x2 %0, %1, %2, %0;" : "+l"(d) : "l"(a), "l"(b));
}

// Stage one 32-wide k-chunk of W (OUTW rows) into dst as kk-major float2 pairs:
// dst[kk2*256 + o] = (W[o][k0+2*kk2], W[o][k0+2*kk2+1]). Conflict-free STS/LDS.
template<int OUTW>
__device__ __forceinline__ void stage_chunk(const float* __restrict__ Wg, int in_act,
                                            int k0, float2* __restrict__ dst, int tid) {
    const bool aligned = ((in_act & 1) == 0);
#pragma unroll 1
    for (int idx = tid; idx < OUTW * 16; idx += THREADS) {
        int o   = idx & (OUTW - 1);
        int kk2 = idx / OUTW;
        int k   = k0 + (kk2 << 1);
        const float* row = Wg + o * in_act;
        float2 v;
        if (aligned && k < in_act) {
            v = __ldg(reinterpret_cast<const float2*>(row + k));
        } else {
            v.x = (k     < in_act) ? __ldg(row + k)     : 0.0f;
            v.y = (k + 1 < in_act) ? __ldg(row + k + 1) : 0.0f;
        }
        dst[kk2 * 256 + o] = v;
    }
}

// Load one k-pair's operands: 8 broadcast activation pairs + NJ weight pairs.
template<int NJ>
__device__ __forceinline__ void load_ops(const float* __restrict__ As, int lda,
                                         const float2* __restrict__ wb, int kk2,
                                         int mb, int lane, ull* a, ull* w) {
#pragma unroll
    for (int i = 0; i < 8; ++i)    // warp-uniform address -> LDS broadcast
        a[i] = *reinterpret_cast<const ull*>(As + (mb + i) * lda + (kk2 << 1));
#pragma unroll
    for (int j = 0; j < NJ; ++j)   // lane-consecutive float2 -> conflict-free
        w[j] = *reinterpret_cast<const ull*>(wb + kk2 * 256 + lane + (j << 5));
}

template<int NJ>
__device__ __forceinline__ void fma_blk(ull (*acc)[NJ], const ull* a, const ull* w) {
#pragma unroll
    for (int j = 0; j < NJ; ++j)
#pragma unroll
        for (int i = 0; i < 8; ++i) fma2(acc[i][j], a[i], w[j]);
}

// Fused layer: xbuf[64][OUT] = relu(A * W^T + b). A chunks from xbuf then emb.
// 8 warps; per-thread tile 8m x NJ o (m = warp*8+i, o = lane+32*j). k in pairs;
// accumulator halves hold even/odd-k partial sums (bias pre-loaded into lo half).
template<int NJ>
__device__ __forceinline__ void gemm_layer(
    const float* __restrict__ Wg, const float* __restrict__ bg,
    int in_act, int nchunks, int xchunks,
    float* xbuf, float* emb, float2* ws2)
{
    constexpr int OUTW = NJ * 32;
    const int tid  = threadIdx.x;
    const int lane = tid & 31;
    const int mb   = (tid >> 5) << 3;

    ull acc[8][NJ];
#pragma unroll
    for (int j = 0; j < NJ; ++j) {
        ull binit = (ull)__float_as_uint(__ldg(bg + lane + (j << 5)));  // lo=bias, hi=0
#pragma unroll
        for (int i = 0; i < 8; ++i) acc[i][j] = binit;
    }

    // prologue: stage chunk 0 into buffer 0 (writes ws only; barrier below orders it)
    stage_chunk<OUTW>(Wg, in_act, 0, ws2, tid);

#pragma unroll 1
    for (int c = 0; c < nchunks; ++c) {
        __syncthreads();   // chunk c staged; prior reads of the other buffer done
        if (c + 1 < nchunks)
            stage_chunk<OUTW>(Wg, in_act, (c + 1) << 5, ws2 + ((c + 1) & 1) * 4096, tid);

        const float* As; int lda;
        if (c < xchunks) { As = xbuf + (c << 5);             lda = 256; }
        else             { As = emb  + ((c - xchunks) << 5); lda = 64;  }
        const float2* wb = ws2 + (c & 1) * 4096;

        // software-pipelined k-pair loop (ping-pong register sets, no rotation)
        ull a0[8], w0[NJ], a1[8], w1[NJ];
        load_ops<NJ>(As, lda, wb, 0, mb, lane, a0, w0);
#pragma unroll 1
        for (int kk2 = 0; kk2 < 16; kk2 += 2) {
            load_ops<NJ>(As, lda, wb, kk2 + 1, mb, lane, a1, w1);
            fma_blk<NJ>(acc, a0, w0);
            load_ops<NJ>(As, lda, wb, kk2 + 2, mb, lane, a0, w0);  // kk2=14 overreads into pad
            fma_blk<NJ>(acc, a1, w1);
        }
    }
    __syncthreads();   // all reads of xbuf done before overwrite
#pragma unroll
    for (int j = 0; j < NJ; ++j) {
        const int o = lane + (j << 5);
#pragma unroll
        for (int i = 0; i < 8; ++i) {
            float lo = __uint_as_float((unsigned)(acc[i][j] & 0xffffffffull));
            float hi = __uint_as_float((unsigned)(acc[i][j] >> 32));
            xbuf[(mb + i) * 256 + o] = fmaxf(lo + hi, 0.0f);
        }
    }
    __syncthreads();
}

__global__ void __launch_bounds__(THREADS, 1) nerf_fused(
    const float* __restrict__ sp,   const float* __restrict__ dirs,
    const float* __restrict__ Wx0,  const float* __restrict__ bx0,
    const float* __restrict__ Wx1,  const float* __restrict__ bx1,
    const float* __restrict__ Wx2,  const float* __restrict__ bx2,
    const float* __restrict__ Wx3,  const float* __restrict__ bx3,
    const float* __restrict__ Wx4,  const float* __restrict__ bx4,
    const float* __restrict__ Wx5,  const float* __restrict__ bx5,
    const float* __restrict__ Wx6,  const float* __restrict__ bx6,
    const float* __restrict__ Wx7,  const float* __restrict__ bx7,
    const float* __restrict__ Wd0,  const float* __restrict__ bd0,
    const float* __restrict__ Wden, const float* __restrict__ bden,
    const float* __restrict__ Wfeat,const float* __restrict__ bfeat,
    const float* __restrict__ Wrgb, const float* __restrict__ brgb,
    float* __restrict__ out)
{
    extern __shared__ float sm[];
    float*  xbuf = sm + XBUF_OFF;
    float*  emb  = sm + EMB_OFF;
    float2* ws2  = reinterpret_cast<float2*>(sm + WS_OFF);
    float*  dens = sm + DENS_OFF;
    float*  embd = sm + EMBD_OFF;

    const int tid  = threadIdx.x;
    const int lane = tid & 31;
    const int warp = tid >> 5;
    const int p0   = blockIdx.x << 6;   // one ray (64 samples) per block

    // ---- Phase 0: xyz harmonic embedding [sin(30), cos(30), xyz(3), pad0] ----
    if (tid < 64) {
        const float* pp = sp + (size_t)(p0 + tid) * 3;
        float* e = emb + tid * 64;
#pragma unroll
        for (int d = 0; d < 3; ++d) {
            float x = pp[d];
            float f = 1.0f;
#pragma unroll
            for (int h = 0; h < 10; ++h) {
                float s, c;
                sincosf(x * f, &s, &c);
                e[d * 10 + h]      = s;
                e[30 + d * 10 + h] = c;
                f *= 2.0f;
            }
            e[60 + d] = x;
        }
        e[63] = 0.0f;
    }
    // gemm_layer's loop-top __syncthreads orders phase 0 vs first compute

    gemm_layer<8>(Wx0, bx0,  63,  2, 0, xbuf, emb, ws2);   // 63->256 (from emb)
    gemm_layer<8>(Wx1, bx1, 256,  8, 8, xbuf, emb, ws2);
    gemm_layer<8>(Wx2, bx2, 256,  8, 8, xbuf, emb, ws2);
    gemm_layer<8>(Wx3, bx3, 256,  8, 8, xbuf, emb, ws2);
    gemm_layer<8>(Wx4, bx4, 319, 10, 8, xbuf, emb, ws2);   // skip: [h(256), emb_x(63)]
    gemm_layer<8>(Wx5, bx5, 256,  8, 8, xbuf, emb, ws2);
    gemm_layer<8>(Wx6, bx6, 256,  8, 8, xbuf, emb, ws2);
    gemm_layer<8>(Wx7, bx7, 256,  8, 8, xbuf, emb, ws2);

    // ---- density head (reads xbuf before feat overwrites it) ----
    {
        const float bd = __ldg(bden);
#pragma unroll 1
        for (int it = 0; it < 8; ++it) {
            int m = warp + (it << 3);
            float s = 0.0f;
#pragma unroll
            for (int kk = 0; kk < 8; ++kk) {
                int k = lane + (kk << 5);
                s += xbuf[m * 256 + k] * __ldg(Wden + k);
            }
#pragma unroll
            for (int off = 16; off > 0; off >>= 1) s += __shfl_xor_sync(0xffffffffu, s, off);
            if (lane == 0) dens[m] = fmaxf(s + bd, 0.0f);
        }
    }
    __syncthreads();

    gemm_layer<8>(Wfeat, bfeat, 256, 8, 8, xbuf, emb, ws2);

    // ---- direction embedding [sin(12), cos(12), dir(3), pad0] -> emb cols 0..31 ----
    if (tid < 32) {
        float v = 0.0f;
        if (tid < 12) {
            float x = __ldg(dirs + blockIdx.x * 3 + (tid >> 2));
            v = sinf(x * (float)(1 << (tid & 3)));
        } else if (tid < 24) {
            int kk = tid - 12;
            float x = __ldg(dirs + blockIdx.x * 3 + (kk >> 2));
            v = cosf(x * (float)(1 << (kk & 3)));
        } else if (tid < 27) {
            v = __ldg(dirs + blockIdx.x * 3 + (tid - 24));
        }
        embd[tid] = v;
    }
    __syncthreads();
    for (int idx = tid; idx < 64 * 32; idx += THREADS)
        emb[(idx >> 5) * 64 + (idx & 31)] = embd[idx & 31];

    gemm_layer<4>(Wd0, bd0, 283, 9, 8, xbuf, emb, ws2);    // [feat(256), emb_d(27)] -> 128

    // ---- rgb head + output ----
    {
#pragma unroll 1
        for (int it = 0; it < 8; ++it) {
            int m = warp + (it << 3);
            float s0 = 0.0f, s1 = 0.0f, s2 = 0.0f;
#pragma unroll
            for (int kk = 0; kk < 4; ++kk) {
                int k = lane + (kk << 5);
                float h = xbuf[m * 256 + k];
                s0 += h * __ldg(Wrgb + k);
                s1 += h * __ldg(Wrgb + 128 + k);
                s2 += h * __ldg(Wrgb + 256 + k);
            }
#pragma unroll
            for (int off = 16; off > 0; off >>= 1) {
                s0 += __shfl_xor_sync(0xffffffffu, s0, off);
                s1 += __shfl_xor_sync(0xffffffffu, s1, off);
                s2 += __shfl_xor_sync(0xffffffffu, s2, off);
            }
            if (lane == 0) {
                float* op = out + (size_t)(p0 + m) * 4;
                op[0] = dens[m];
                op[1] = 1.0f / (1.0f + expf(-(s0 + __ldg(brgb))));
                op[2] = 1.0f / (1.0f + expf(-(s1 + __ldg(brgb + 1))));
                op[3] = 1.0f / (1.0f + expf(-(s2 + __ldg(brgb + 2))));
            }
        }
    }
}

extern "C" void kernel_launch(void* const* d_in, const int* in_sizes, int n_in,
                              void* d_out, int out_size) {
    (void)in_sizes; (void)n_in; (void)out_size;
    cudaFuncSetAttribute(nerf_fused, cudaFuncAttributeMaxDynamicSharedMemorySize, SMEM_BYTES);
    nerf_fused<<<4096, THREADS, SMEM_BYTES>>>(
        (const float*)d_in[0],  (const float*)d_in[1],
        (const float*)d_in[2],  (const float*)d_in[3],
        (const float*)d_in[4],  (const float*)d_in[5],
        (const float*)d_in[6],  (const float*)d_in[7],
        (const float*)d_in[8],  (const float*)d_in[9],
        (const float*)d_in[10], (const float*)d_in[11],
        (const float*)d_in[12], (const float*)d_in[13],
        (const float*)d_in[14], (const float*)d_in[15],
        (const float*)d_in[16], (const float*)d_in[17],
        (const float*)d_in[18], (const float*)d_in[19],
        (const float*)d_in[20], (const float*)d_in[21],
        (const float*)d_in[22], (const float*)d_in[23],
        (const float*)d_in[24], (const float*)d_in[25],
        (float*)d_out);
}